// round 12
// baseline (speedup 1.0000x reference)
#include <cuda_runtime.h>
#include <cstdint>

// HexPool: out[i, :] = max_{k<7} x[neigh_indices[i,k], :]
// x: (655362, 64) f32 ; neigh_indices: (163842, 7) int32 ; out: (163842, 64) f32
//
// FINAL (R7 shape, best of 8 measured variants @ 22.1us):
//  - 16 threads (one half-warp) per output row, one float4 per thread:
//    each gather warp-instruction touches only 2 distinct rows (minimal
//    L1tex wavefronts). 8-thread/row + LDG.256/policy-hint hybrids all lost
//    1-3us in A/B tests (R8/R10/R11).
//  - Indices broadcast via one SHFL each; all lanes converged (tail clamps
//    row, predicates only the store).
//  - Output stores __stcs (evict-first): keeps the 42MB x gather region
//    L2-resident, -10% (R7's win).
// Bottleneck: ~340 MB/launch through L2 at ~15.4 TB/s effective -- the L2-hit
// bandwidth floor for an algorithmically irreducible random gather.

#define N_OUT 163842
#define KNB   7
#define VEC_PER_ROW 16   // 64 floats / 4

__global__ __launch_bounds__(256) void hexpool_kernel(
    const float4* __restrict__ x,          // viewed as [n_in][16] float4
    const int* __restrict__ idx,           // [N_OUT][7] int32
    float4* __restrict__ out)               // [N_OUT][16] float4
{
    const int gid = blockIdx.x * blockDim.x + threadIdx.x;
    const int row_raw = gid >> 4;                 // output row (may overshoot in tail)
    const int row = row_raw < N_OUT ? row_raw : (N_OUT - 1);
    const int col = gid & 15;                     // float4 column within row

    const int lane = threadIdx.x & 31;
    const int half_base = lane & 16;              // 0 or 16: start lane of my half-warp
    const int sub = lane & 15;

    // Lanes sub<7 of each half-warp load the 7 indices for this half-warp's row.
    int my_idx = 0;
    if (sub < KNB) {
        my_idx = __ldg(&idx[row * KNB + sub]);
    }

    float4 m = make_float4(-3.402823466e+38f, -3.402823466e+38f,
                           -3.402823466e+38f, -3.402823466e+38f);

    #pragma unroll
    for (int k = 0; k < KNB; ++k) {
        int j = __shfl_sync(0xFFFFFFFFu, my_idx, half_base + k);
        float4 v = __ldg(&x[(long long)j * VEC_PER_ROW + col]);
        m.x = fmaxf(m.x, v.x);
        m.y = fmaxf(m.y, v.y);
        m.z = fmaxf(m.z, v.z);
        m.w = fmaxf(m.w, v.w);
    }

    if (row_raw < N_OUT) {
        __stcs(&out[gid], m);   // evict-first: don't displace x's L2 lines
    }
}

extern "C" void kernel_launch(void* const* d_in, const int* in_sizes, int n_in,
                              void* d_out, int out_size)
{
    const float4* x   = (const float4*)d_in[0];
    const int*    idx = (const int*)d_in[1];
    float4*       out = (float4*)d_out;

    const int total_threads = N_OUT * VEC_PER_ROW;   // 2,621,472
    const int block = 256;
    const int grid  = (total_threads + block - 1) / block;
    hexpool_kernel<<<grid, block>>>(x, idx, out);
}

// round 13
// speedup vs baseline: 1.0111x; 1.0111x over previous
#include <cuda_runtime.h>
#include <cstdint>

// HexPool: out[i, :] = max_{k<7} x[neigh_indices[i,k], :]
// x: (655362, 64) f32 ; neigh_indices: (163842, 7) int32 ; out: (163842, 64) f32
//
// Winning shape (R7, 22.1us; re-bench 23.3us -> run noise ~±1us):
//  - 16 threads (one half-warp) per output row, one float4 per thread:
//    each gather warp-instruction touches only 2 distinct rows (minimal
//    L1tex wavefronts). All 8-thread/row / LDG.256 / policy-hint hybrids
//    measured slower (R8/R10/R11).
//  - Indices broadcast via one SHFL each; all lanes converged (tail clamps
//    row, predicates only the store).
//  - Output stores __stcs (evict-first): keeps the 42MB x gather region
//    L2-resident (the one reproducible -10% win).
// This round's only delta: 512-thread blocks (untested axis; occ was 59.5%
// with no resource limiter). Traffic unchanged: ~340MB/launch through L2,
// which is the algorithmic transport floor for this random gather.

#define N_OUT 163842
#define KNB   7
#define VEC_PER_ROW 16   // 64 floats / 4
#define BLOCK_THREADS 512

__global__ __launch_bounds__(BLOCK_THREADS) void hexpool_kernel(
    const float4* __restrict__ x,          // viewed as [n_in][16] float4
    const int* __restrict__ idx,           // [N_OUT][7] int32
    float4* __restrict__ out)               // [N_OUT][16] float4
{
    const int gid = blockIdx.x * BLOCK_THREADS + threadIdx.x;
    const int row_raw = gid >> 4;                 // output row (may overshoot in tail)
    const int row = row_raw < N_OUT ? row_raw : (N_OUT - 1);
    const int col = gid & 15;                     // float4 column within row

    const int lane = threadIdx.x & 31;
    const int half_base = lane & 16;              // 0 or 16: start lane of my half-warp
    const int sub = lane & 15;

    // Lanes sub<7 of each half-warp load the 7 indices for this half-warp's row.
    int my_idx = 0;
    if (sub < KNB) {
        my_idx = __ldg(&idx[row * KNB + sub]);
    }

    float4 m = make_float4(-3.402823466e+38f, -3.402823466e+38f,
                           -3.402823466e+38f, -3.402823466e+38f);

    #pragma unroll
    for (int k = 0; k < KNB; ++k) {
        int j = __shfl_sync(0xFFFFFFFFu, my_idx, half_base + k);
        float4 v = __ldg(&x[(long long)j * VEC_PER_ROW + col]);
        m.x = fmaxf(m.x, v.x);
        m.y = fmaxf(m.y, v.y);
        m.z = fmaxf(m.z, v.z);
        m.w = fmaxf(m.w, v.w);
    }

    if (row_raw < N_OUT) {
        __stcs(&out[gid], m);   // evict-first: don't displace x's L2 lines
    }
}

extern "C" void kernel_launch(void* const* d_in, const int* in_sizes, int n_in,
                              void* d_out, int out_size)
{
    const float4* x   = (const float4*)d_in[0];
    const int*    idx = (const int*)d_in[1];
    float4*       out = (float4*)d_out;

    const int total_threads = N_OUT * VEC_PER_ROW;   // 2,621,472
    const int grid = (total_threads + BLOCK_THREADS - 1) / BLOCK_THREADS;  // 5121
    hexpool_kernel<<<grid, BLOCK_THREADS>>>(x, idx, out);
}